// round 16
// baseline (speedup 1.0000x reference)
#include <cuda_runtime.h>
#include <cstdint>

// Conv2d N=16,C=128,H=W=56,K=128,3x3,pad1 as 9 shifted GEMMs using
// mma.sync.m16n8k16.f32.f16.f16.f32 (base PTX).
// CTA = 128k x 112 pos (2 rows x 56 w), 8 warps, occ 3 (85-reg cap).
// W path is WARP-PRIVATE: each warp cp.asyncs its own 2KB A slice per
// stage into a private smem double-buffer (wait_group + __syncwarp only).
// CTA-wide __syncthreads ONLY at the 4 X c-group boundaries.
// (R15 bug fixed: A fragment read was missing the +lid*4 lane offset.)

typedef uint32_t u32;

#define X_ELEMS 3904                 // u32 half2: [kk:2][lq:4][row:4][122]
#define XB(i)   ((i) * X_ELEMS)
#define APRIV_OFF (2 * X_ELEMS)      // 8 warps x 2 slots x 512 u32
#define SMEM_BYTES ((2 * X_ELEMS + 8 * 2 * 512) * 4)   // 64000

__device__ u32 g_Wh[36 * 2048];      // [slab:36][mgrp:4][mt:2][kk:2][lane:32][4] fp16x2

__global__ void prep_weights(const float* __restrict__ wt) {
    int idx = blockIdx.x * 256 + threadIdx.x;
    if (idx >= 36 * 2048) return;
    int slab   = idx >> 11;
    int within = idx & 2047;
    int vi   = within & 3;           // a-reg index a0..a3
    int lane = (within >> 2) & 31;
    int kk   = (within >> 7) & 1;
    int mt   = (within >> 8) & 1;
    int mgrp = (within >> 9) & 3;
    int cg = slab / 9, rs = slab % 9;
    int k  = mgrp * 32 + mt * 16 + (lane >> 2) + (vi & 1) * 8;
    int c0 = cg * 32 + kk * 16 + (lane & 3) * 2 + (vi >> 1) * 8;
    float v0 = wt[(size_t)k * 1152 + (size_t)c0 * 9 + rs];
    float v1 = wt[(size_t)k * 1152 + (size_t)(c0 + 1) * 9 + rs];
    u32 p;
    asm("cvt.rn.f16x2.f32 %0, %1, %2;" : "=r"(p) : "f"(v1), "f"(v0));
    g_Wh[idx] = p;
}

__global__ __launch_bounds__(256, 3)
void conv_mma(const float* __restrict__ in,
              const float* __restrict__ bias,
              float* __restrict__ out)
{
    extern __shared__ u32 sm[];
    u32 sbase;
    asm("{ .reg .u64 t; cvta.to.shared.u64 t, %1; cvt.u32.u64 %0, t; }"
        : "=r"(sbase) : "l"(sm));

    const int tid = threadIdx.x;
    const int wid = tid >> 5, lid = tid & 31;
    const int lq = lid & 3, g = lid >> 2;
    const int mgrp = wid & 3;             // warp m group (32 k each)
    const int wn = wid >> 2;              // warp output row (0/1)

    // warp-private A buffer: 2 slots x 512 u32
    u32* Apriv = sm + APRIV_OFF + wid * 1024;
    const u32 apriv_base = sbase + (APRIV_OFF + wid * 1024) * 4;

    const int img = blockIdx.x / 28;
    const int h0  = (blockIdx.x % 28) * 2;
    const float* in_n = in + (size_t)img * 401408;

    float acc[2][7][4];
    #pragma unroll
    for (int mt = 0; mt < 2; mt++)
        #pragma unroll
        for (int nt = 0; nt < 7; nt++)
            #pragma unroll
            for (int q = 0; q < 4; q++) acc[mt][nt][q] = 0.f;

    // ---- X loader: LDG fp32 -> cvt.rn.f16x2 -> STS ----
    auto loadX = [&](int cg, int xb) {
        #pragma unroll 1
        for (int idx = tid; idx < 4096; idx += 256) {
            int wl = idx & 63;
            int t  = idx >> 6;           // 0..63
            if (wl < 58) {
                int row = t & 3;
                int hi  = (t >> 2) & 1;
                int lq_ = (t >> 3) & 3;
                int kk_ = t >> 5;
                int hin = h0 - 1 + row;
                int win = wl - 1;
                int c0  = cg * 32 + kk_ * 16 + lq_ * 2 + hi * 8;
                float v0 = 0.f, v1 = 0.f;
                if (((unsigned)hin < 56u) & ((unsigned)win < 56u)) {
                    const float* p = in_n + (size_t)c0 * 3136 + hin * 56 + win;
                    v0 = __ldg(p);
                    v1 = __ldg(p + 3136);
                }
                u32 pk;
                asm("cvt.rn.f16x2.f32 %0, %1, %2;" : "=r"(pk) : "f"(v1), "f"(v0));
                sm[XB(xb) + ((kk_ * 4 + lq_) * 4 + row) * 122 + wl * 2 + hi] = pk;
            }
        }
    };

    // ---- warp-private A prefetch: 4x cp.async 16B per lane, one group ----
    auto prefA = [&](int s) {
        const u32* src = g_Wh + (size_t)s * 2048 + mgrp * 512 + lid * 16;
        const u32 dst  = apriv_base + ((s & 1) * 512 + lid * 16) * 4;
        #pragma unroll
        for (int j = 0; j < 4; j++)
            asm volatile("cp.async.ca.shared.global [%0], [%1], 16;"
                         :: "r"(dst + j * 16), "l"(src + j * 4) : "memory");
        asm volatile("cp.async.commit_group;" ::: "memory");
    };

    // ---- prologue ----
    prefA(0);                 // group A0
    loadX(0, 0);
    __syncthreads();          // X(0) visible CTA-wide

    #pragma unroll 1
    for (int cg = 0; cg < 4; cg++) {
        if (cg > 0) __syncthreads();   // X(cg) visible; old X buffer free

        #pragma unroll 1
        for (int rs = 0; rs < 9; rs++) {
            const int s = cg * 9 + rs;
            if (s + 1 < 36) {
                prefA(s + 1);
                asm volatile("cp.async.wait_group 1;" ::: "memory");
            } else {
                asm volatile("cp.async.wait_group 0;" ::: "memory");
            }
            __syncwarp();     // A(s) slot visible warp-wide

            if (rs == 5 && cg < 3) loadX(cg + 1, (cg + 1) & 1);

            const u32* Wb = Apriv + (s & 1) * 512 + lid * 4;   // lane offset!
            const u32* Bb = sm + XB(cg & 1) + lq * 488
                            + (wn + rs / 3) * 122 + (g + rs % 3) * 2;

            #pragma unroll
            for (int kk = 0; kk < 2; kk++) {
                u32 b[7][2];
                #pragma unroll
                for (int nt = 0; nt < 7; nt++) {
                    uint2 v = *reinterpret_cast<const uint2*>(
                                  Bb + kk * 1952 + nt * 16);
                    b[nt][0] = v.x;
                    b[nt][1] = v.y;
                }
                #pragma unroll
                for (int mt = 0; mt < 2; mt++) {
                    uint4 av = *reinterpret_cast<const uint4*>(
                                   Wb + mt * 256 + kk * 128);
                    #pragma unroll
                    for (int nt = 0; nt < 7; nt++)
                        asm volatile(
                            "mma.sync.aligned.m16n8k16.row.col.f32.f16.f16.f32 "
                            "{%0,%1,%2,%3}, {%4,%5,%6,%7}, {%8,%9}, {%0,%1,%2,%3};"
                            : "+f"(acc[mt][nt][0]), "+f"(acc[mt][nt][1]),
                              "+f"(acc[mt][nt][2]), "+f"(acc[mt][nt][3])
                            : "r"(av.x), "r"(av.y), "r"(av.z), "r"(av.w),
                              "r"(b[nt][0]), "r"(b[nt][1]));
                }
            }
        }
    }

    // ---- epilogue: direct STG.64 + bias ----
    #pragma unroll
    for (int mt = 0; mt < 2; mt++)
        #pragma unroll
        for (int h = 0; h < 2; h++) {
            const int k = mgrp * 32 + mt * 16 + h * 8 + g;
            const float bv = __ldg(&bias[k]);
            float* op = out + (size_t)img * 401408 + (size_t)k * 3136
                        + (h0 + wn) * 56 + lq * 2;
            #pragma unroll
            for (int nt = 0; nt < 7; nt++) {
                float2 v;
                v.x = acc[mt][nt][2 * h + 0] + bv;
                v.y = acc[mt][nt][2 * h + 1] + bv;
                *reinterpret_cast<float2*>(op + nt * 8) = v;
            }
        }
}

extern "C" void kernel_launch(void* const* d_in, const int* in_sizes, int n_in,
                              void* d_out, int out_size)
{
    const float* input  = (const float*)d_in[0];
    const float* weight = (const float*)d_in[1];
    const float* bias   = (const float*)d_in[2];
    float* out = (float*)d_out;

    cudaFuncSetAttribute(conv_mma, cudaFuncAttributeMaxDynamicSharedMemorySize,
                         SMEM_BYTES);
    cudaFuncSetAttribute(conv_mma,
                         cudaFuncAttributePreferredSharedMemoryCarveout, 100);

    prep_weights<<<(36 * 2048 + 255) / 256, 256>>>(weight);
    conv_mma<<<448, 256, SMEM_BYTES>>>(input, bias, out);
}

// round 17
// speedup vs baseline: 1.2869x; 1.2869x over previous
#include <cuda_runtime.h>
#include <cstdint>

// Conv2d N=16,C=128,H=W=56,K=128,3x3,pad1 as 9 shifted GEMMs using
// mma.sync.m16n8k16.f32.f16.f16.f32 (base PTX).
// CTA = 128k x 112 pos (2 rows x 56 w), 8 warps, occ 3 (85-reg cap).
// R14 paired-stage pipeline (one barrier + one 16KB cp.async W group per
// TWO stages, 4-slot ring) + X loads SPREAD in 3 chunks across pair
// bodies so the post-barrier load burst interleaves with HMMAs.

typedef uint32_t u32;

#define X_ELEMS 3904                 // u32 half2: [kk:2][lq:4][row:4][122]
#define W_ELEMS 2048                 // u32 per slab: [mgrp:4][mt:2][kk:2][lane:32][4]
#define XB(i)   ((i) * X_ELEMS)
#define WB(i)   (2 * X_ELEMS + (i) * W_ELEMS)
#define SMEM_BYTES ((2 * X_ELEMS + 4 * W_ELEMS) * 4)   // 64000

__device__ u32 g_Wh[36 * 2048];      // fragment-ordered fp16x2 slabs

__global__ void prep_weights(const float* __restrict__ wt) {
    int idx = blockIdx.x * 256 + threadIdx.x;
    if (idx >= 36 * 2048) return;
    int slab   = idx >> 11;
    int within = idx & 2047;
    int vi   = within & 3;           // a-reg index a0..a3
    int lane = (within >> 2) & 31;
    int kk   = (within >> 7) & 1;
    int mt   = (within >> 8) & 1;
    int mgrp = (within >> 9) & 3;
    int cg = slab / 9, rs = slab % 9;
    int k  = mgrp * 32 + mt * 16 + (lane >> 2) + (vi & 1) * 8;
    int c0 = cg * 32 + kk * 16 + (lane & 3) * 2 + (vi >> 1) * 8;
    float v0 = wt[(size_t)k * 1152 + (size_t)c0 * 9 + rs];
    float v1 = wt[(size_t)k * 1152 + (size_t)(c0 + 1) * 9 + rs];
    u32 p;
    asm("cvt.rn.f16x2.f32 %0, %1, %2;" : "=r"(p) : "f"(v1), "f"(v0));
    g_Wh[idx] = p;
}

__global__ __launch_bounds__(256, 3)
void conv_mma(const float* __restrict__ in,
              const float* __restrict__ bias,
              float* __restrict__ out)
{
    extern __shared__ u32 sm[];
    u32 sbase;
    asm("{ .reg .u64 t; cvta.to.shared.u64 t, %1; cvt.u32.u64 %0, t; }"
        : "=r"(sbase) : "l"(sm));

    const int tid = threadIdx.x;
    const int wid = tid >> 5, lid = tid & 31;
    const int lq = lid & 3, g = lid >> 2;
    const int mgrp = wid & 3;             // warp m group (32 k each)
    const int wn = wid >> 2;              // warp output row (0/1)

    const int img = blockIdx.x / 28;
    const int h0  = (blockIdx.x % 28) * 2;
    const float* in_n = in + (size_t)img * 401408;

    float acc[2][7][4];
    #pragma unroll
    for (int mt = 0; mt < 2; mt++)
        #pragma unroll
        for (int nt = 0; nt < 7; nt++)
            #pragma unroll
            for (int q = 0; q < 4; q++) acc[mt][nt][q] = 0.f;

    // ---- X loader chunk: iterations [i0,i1] of the 16-iteration sweep ----
    auto loadXpart = [&](int cg, int xb, int i0, int i1) {
        #pragma unroll 1
        for (int i = i0; i <= i1; i++) {
            int idx = tid + i * 256;
            int wl = idx & 63;
            int t  = idx >> 6;           // 0..63
            if (wl < 58) {
                int row = t & 3;
                int hi  = (t >> 2) & 1;
                int lq_ = (t >> 3) & 3;
                int kk_ = t >> 5;
                int hin = h0 - 1 + row;
                int win = wl - 1;
                int c0  = cg * 32 + kk_ * 16 + lq_ * 2 + hi * 8;
                float v0 = 0.f, v1 = 0.f;
                if (((unsigned)hin < 56u) & ((unsigned)win < 56u)) {
                    const float* p = in_n + (size_t)c0 * 3136 + hin * 56 + win;
                    v0 = __ldg(p);
                    v1 = __ldg(p + 3136);
                }
                u32 pk;
                asm("cvt.rn.f16x2.f32 %0, %1, %2;" : "=r"(pk) : "f"(v1), "f"(v0));
                sm[XB(xb) + ((kk_ * 4 + lq_) * 4 + row) * 122 + wl * 2 + hi] = pk;
            }
        }
    };

    // ---- async W loader: pair of slabs (16KB) as ONE cp.async group ----
    auto prefWpair = [&](int p) {
        #pragma unroll
        for (int j = 0; j < 2; j++) {
            int slab = 2 * p + j;
            const u32* src = g_Wh + (size_t)slab * 2048;
            const u32 dstb = sbase + WB(slab & 3) * 4;
            #pragma unroll
            for (int c = 0; c < 2; c++) {
                int chunk = tid + c * 256;         // 0..511, 16B each
                asm volatile("cp.async.ca.shared.global [%0], [%1], 16;"
                             :: "r"(dstb + chunk * 16), "l"(src + chunk * 4)
                             : "memory");
            }
        }
        asm volatile("cp.async.commit_group;" ::: "memory");
    };

    // ---- one GEMM stage ----
    auto computeStage = [&](int s) {
        const int rs = s % 9;
        const u32* Wb = sm + WB(s & 3) + mgrp * 512 + lid * 4;
        const u32* Bb = sm + XB((s / 9) & 1) + lq * 488
                        + (wn + rs / 3) * 122 + (g + rs % 3) * 2;
        #pragma unroll
        for (int kk = 0; kk < 2; kk++) {
            u32 b[7][2];
            #pragma unroll
            for (int nt = 0; nt < 7; nt++) {
                uint2 v = *reinterpret_cast<const uint2*>(
                              Bb + kk * 1952 + nt * 16);
                b[nt][0] = v.x;
                b[nt][1] = v.y;
            }
            #pragma unroll
            for (int mt = 0; mt < 2; mt++) {
                uint4 av = *reinterpret_cast<const uint4*>(
                               Wb + mt * 256 + kk * 128);
                #pragma unroll
                for (int nt = 0; nt < 7; nt++)
                    asm volatile(
                        "mma.sync.aligned.m16n8k16.row.col.f32.f16.f16.f32 "
                        "{%0,%1,%2,%3}, {%4,%5,%6,%7}, {%8,%9}, {%0,%1,%2,%3};"
                        : "+f"(acc[mt][nt][0]), "+f"(acc[mt][nt][1]),
                          "+f"(acc[mt][nt][2]), "+f"(acc[mt][nt][3])
                        : "r"(av.x), "r"(av.y), "r"(av.z), "r"(av.w),
                          "r"(b[nt][0]), "r"(b[nt][1]));
            }
        }
    };

    // ---- prologue: G0 (slabs 0,1) + full X(0) ----
    prefWpair(0);
    loadXpart(0, 0, 0, 15);
    asm volatile("cp.async.wait_group 0;" ::: "memory");
    __syncthreads();

    #pragma unroll 1
    for (int p = 0; p < 18; p++) {
        if (p > 0) {
            asm volatile("cp.async.wait_group 0;" ::: "memory");
            __syncthreads();   // G_p + prior X chunks visible; prior reads done
        }
        if (p + 1 < 18) prefWpair(p + 1);   // slots freed by pair p-1 reads

        // X chunks spread across 3 pair bodies per c-group:
        //   cg1 @ p=1,2,3  (first read s=9,  pair 4  -> barrier p4 orders)
        //   cg2 @ p=5,6,7  (first read s=18, pair 9;  buf0 free after pair 4)
        //   cg3 @ p=9,10,11(first read s=27, pair 13; buf1 free after pair 8)
        if (p >= 1 && p <= 3) {
            int c = p - 1;
            loadXpart(1, 1, c == 0 ? 0 : (c == 1 ? 6 : 11),
                            c == 0 ? 5 : (c == 1 ? 10 : 15));
        } else if (p >= 5 && p <= 7) {
            int c = p - 5;
            loadXpart(2, 0, c == 0 ? 0 : (c == 1 ? 6 : 11),
                            c == 0 ? 5 : (c == 1 ? 10 : 15));
        } else if (p >= 9 && p <= 11) {
            int c = p - 9;
            loadXpart(3, 1, c == 0 ? 0 : (c == 1 ? 6 : 11),
                            c == 0 ? 5 : (c == 1 ? 10 : 15));
        }

        computeStage(2 * p);
        computeStage(2 * p + 1);
    }

    // ---- epilogue: direct STG.64 + bias ----
    #pragma unroll
    for (int mt = 0; mt < 2; mt++)
        #pragma unroll
        for (int h = 0; h < 2; h++) {
            const int k = mgrp * 32 + mt * 16 + h * 8 + g;
            const float bv = __ldg(&bias[k]);
            float* op = out + (size_t)img * 401408 + (size_t)k * 3136
                        + (h0 + wn) * 56 + lq * 2;
            #pragma unroll
            for (int nt = 0; nt < 7; nt++) {
                float2 v;
                v.x = acc[mt][nt][2 * h + 0] + bv;
                v.y = acc[mt][nt][2 * h + 1] + bv;
                *reinterpret_cast<float2*>(op + nt * 8) = v;
            }
        }
}

extern "C" void kernel_launch(void* const* d_in, const int* in_sizes, int n_in,
                              void* d_out, int out_size)
{
    const float* input  = (const float*)d_in[0];
    const float* weight = (const float*)d_in[1];
    const float* bias   = (const float*)d_in[2];
    float* out = (float*)d_out;

    cudaFuncSetAttribute(conv_mma, cudaFuncAttributeMaxDynamicSharedMemorySize,
                         SMEM_BYTES);
    cudaFuncSetAttribute(conv_mma,
                         cudaFuncAttributePreferredSharedMemoryCarveout, 100);

    prep_weights<<<(36 * 2048 + 255) / 256, 256>>>(weight);
    conv_mma<<<448, 256, SMEM_BYTES>>>(input, bias, out);
}